// round 2
// baseline (speedup 1.0000x reference)
#include <cuda_runtime.h>
#include <cstdint>

#define DI __device__ __forceinline__

// ---------------- scratch (device globals; no allocation allowed) ----------
__device__ float g_t1[192 * 192];          // [p=(Ii,Oo)][r2]     147 KB
__device__ float g_C [48 * 128 * 384];     // GEMM out buf, reused 9.4 MB
__device__ float g_t2[48 * 128 * 384];     // [Ii2][Oo2][q]        9.4 MB
__device__ float g_t3[192 * 768 * 16];     // [Ii3][Oo3][q]        9.4 MB
__device__ float g_M [768 * 3072];         // final matrix         9.4 MB

// ---------------- helpers ---------------------------------------------------
DI float tf32r(float x) {
    uint32_t u;
    asm("cvt.rna.tf32.f32 %0, %1;" : "=r"(u) : "f"(x));
    return __uint_as_float(u);
}

DI void mma_tf32(float c[4], const uint32_t a[4], const uint32_t b[2]) {
    asm("mma.sync.aligned.m16n8k8.row.col.f32.tf32.tf32.f32 "
        "{%0,%1,%2,%3}, {%4,%5,%6,%7}, {%8,%9}, {%0,%1,%2,%3};"
        : "+f"(c[0]), "+f"(c[1]), "+f"(c[2]), "+f"(c[3])
        : "r"(a[0]), "r"(a[1]), "r"(a[2]), "r"(a[3]),
          "r"(b[0]), "r"(b[1]));
}

// ---------------- step 1: t1[(Ii,Oo)][q] = sum_r core0 * core1 --------------
// core0 [1,3,4,12], core1 [12,4,4,192]; output [192][192]
__global__ void k_t1(const float* __restrict__ c0, const float* __restrict__ c1) {
    int idx = blockIdx.x * blockDim.x + threadIdx.x;
    if (idx >= 192 * 192) return;
    int p = idx / 192, q = idx % 192;
    int Ii = p >> 4, Oo = p & 15;
    int I = Ii >> 2, i = Ii & 3, O = Oo >> 2, o = Oo & 3;
    float acc = 0.f;
#pragma unroll
    for (int r = 0; r < 12; ++r)
        acc += c0[(I * 4 + O) * 12 + r] * c1[((r * 4 + i) * 4 + o) * 192 + q];
    g_t1[idx] = acc;
}

// ---------------- mid GEMM (fp32): C = A[M,K] * B[K,N], all row-major -------
// STEP==0: A=g_t1 (192x192),  B=core2, C=g_C (192x12288)
// STEP==1: A=g_t2 (6144x384), B=core3, C=g_C (6144x384)
// Dims divisible by BM=64, BN=64, BK=16. 256 threads, 4x4 per thread.
template <int STEP>
__global__ void gemm_mid(const float* __restrict__ B, int M, int N, int K) {
    const float* __restrict__ A = (STEP == 0) ? g_t1 : g_t2;
    float* __restrict__ C = g_C;

    __shared__ float As[16][68];   // transposed A tile [k][m], padded
    __shared__ float Bs[16][64];   // [k][n]

    int tid = threadIdx.x;
    int bm = blockIdx.y * 64, bn = blockIdx.x * 64;
    int row = (tid / 16) * 4, col = (tid % 16) * 4;

    float acc[4][4] = {};

    int arow = tid >> 2;          // 0..63
    int ac   = (tid & 3) * 4;     // 0,4,8,12
    int brow = tid >> 4;          // 0..15
    int bc   = (tid & 15) * 4;    // 0..60

    for (int kt = 0; kt < K; kt += 16) {
        float4 av = *(const float4*)&A[(size_t)(bm + arow) * K + kt + ac];
        float4 bv = *(const float4*)&B[(size_t)(kt + brow) * N + bn + bc];
        __syncthreads();
        As[ac + 0][arow] = av.x;
        As[ac + 1][arow] = av.y;
        As[ac + 2][arow] = av.z;
        As[ac + 3][arow] = av.w;
        *(float4*)&Bs[brow][bc] = bv;
        __syncthreads();
#pragma unroll
        for (int kk = 0; kk < 16; ++kk) {
            float4 a = *(const float4*)&As[kk][row];
            float4 b = *(const float4*)&Bs[kk][col];
            float aa[4] = {a.x, a.y, a.z, a.w};
            float bb[4] = {b.x, b.y, b.z, b.w};
#pragma unroll
            for (int ii = 0; ii < 4; ++ii)
#pragma unroll
                for (int jj = 0; jj < 4; ++jj)
                    acc[ii][jj] += aa[ii] * bb[jj];
        }
    }
#pragma unroll
    for (int ii = 0; ii < 4; ++ii)
#pragma unroll
        for (int jj = 0; jj < 4; ++jj)
            C[(size_t)(bm + row + ii) * N + bn + col + jj] = acc[ii][jj];
}

// ---------------- reindex after step 2 --------------------------------------
// g_t2[Ii2][Oo2][q] = g_C[(Ii*16+Oo)][(i*8+o)*384+q]; Ii2=Ii*4+i, Oo2=Oo*8+o
__global__ void k_reidx2() {
    int idx = blockIdx.x * 256 + threadIdx.x;   // < 48*128*384
    int q = idx % 384;
    int t = idx / 384;
    int Oo2 = t % 128, Ii2 = t / 128;
    int Ii = Ii2 >> 2, i = Ii2 & 3, Oo = Oo2 >> 3, o = Oo2 & 7;
    g_t2[idx] = g_C[(size_t)(Ii * 16 + Oo) * 12288 + (i * 8 + o) * 384 + q];
}

// ---------------- reindex after step 3 --------------------------------------
// g_t3[Ii3][Oo3][q] = g_C[(Ii2*128+Oo2)][(i3*6+o3)*16+q]; Ii3=Ii2*4+i3, Oo3=Oo2*6+o3
__global__ void k_reidx3() {
    int idx = blockIdx.x * 256 + threadIdx.x;   // < 192*768*16
    int q = idx & 15;
    int t = idx >> 4;
    int Oo3 = t % 768, Ii3 = t / 768;
    int Ii2 = Ii3 >> 2, i3 = Ii3 & 3;
    int Oo2 = Oo3 / 6, o3 = Oo3 % 6;
    g_t3[idx] = g_C[(size_t)(Ii2 * 128 + Oo2) * 384 + (i3 * 6 + o3) * 16 + q];
}

// ---------------- step 4 fused: M = t3 x core4, reindexed -------------------
// core4 [16,4,4,1] -> Bs[q*16 + i4*4 + o4]
__global__ void k_t4(const float* __restrict__ c4) {
    __shared__ float Bs[256];
    int tid = threadIdx.x;
    Bs[tid] = c4[tid];
    __syncthreads();
    int p = blockIdx.x * 256 + tid;   // < 147456 rows of t3 [.,16]
    float a[16];
#pragma unroll
    for (int j = 0; j < 4; ++j) {
        float4 v = *(const float4*)&g_t3[(size_t)p * 16 + j * 4];
        a[j * 4 + 0] = v.x; a[j * 4 + 1] = v.y; a[j * 4 + 2] = v.z; a[j * 4 + 3] = v.w;
    }
    int Ii3 = p / 768, Oo3 = p % 768;
#pragma unroll
    for (int n = 0; n < 16; ++n) {
        float acc = 0.f;
#pragma unroll
        for (int q = 0; q < 16; ++q) acc += a[q] * Bs[q * 16 + n];
        int i4 = n >> 2, o4 = n & 3;
        g_M[(size_t)(Ii3 * 4 + i4) * 3072 + Oo3 * 4 + o4] = acc;
    }
}

// ---------------- main GEMM: Y[32768,3072] = X[32768,768] * g_M + bias ------
// tf32 mma.sync m16n8k8, BM=128 BN=128 BK=32, 8 warps (2x4), warp tile 64x32
__global__ __launch_bounds__(256, 2)
void k_main(const float* __restrict__ X, const float* __restrict__ bias,
            float* __restrict__ Y) {
    __shared__ float As[128][36];   // [m][k], padded (bank-conflict-free frags)
    __shared__ float Bs[32][132];   // [k][n], padded

    int tid  = threadIdx.x;
    int warp = tid >> 5, lane = tid & 31;
    int wm = warp >> 2, wn = warp & 3;     // 2 x 4 warp grid
    int g  = lane >> 2, tg = lane & 3;

    int row0 = blockIdx.y * 128;
    int col0 = blockIdx.x * 128;

    float c[4][4][4] = {};

    // global load mapping
    int arow = tid >> 3;            // 0..31  (A: 128 rows x 8 vec4)
    int acv  = (tid & 7) * 4;
    int brow = tid >> 5;            // 0..7   (B: 32 rows x 32 vec4)
    int bcv  = (tid & 31) * 4;

    float4 pA[4], pB[4];
#pragma unroll
    for (int p = 0; p < 4; ++p)
        pA[p] = *(const float4*)&X[(size_t)(row0 + arow + 32 * p) * 768 + acv];
#pragma unroll
    for (int p = 0; p < 4; ++p)
        pB[p] = *(const float4*)&g_M[(size_t)(brow + 8 * p) * 3072 + col0 + bcv];

    for (int kt = 0; kt < 768; kt += 32) {
        __syncthreads();
#pragma unroll
        for (int p = 0; p < 4; ++p) {
            float4 v = pA[p];
            float4 w = make_float4(tf32r(v.x), tf32r(v.y), tf32r(v.z), tf32r(v.w));
            *(float4*)&As[arow + 32 * p][acv] = w;
        }
#pragma unroll
        for (int p = 0; p < 4; ++p) {
            float4 v = pB[p];
            float4 w = make_float4(tf32r(v.x), tf32r(v.y), tf32r(v.z), tf32r(v.w));
            *(float4*)&Bs[brow + 8 * p][bcv] = w;
        }
        __syncthreads();

        if (kt + 32 < 768) {
#pragma unroll
            for (int p = 0; p < 4; ++p)
                pA[p] = *(const float4*)&X[(size_t)(row0 + arow + 32 * p) * 768 + kt + 32 + acv];
#pragma unroll
            for (int p = 0; p < 4; ++p)
                pB[p] = *(const float4*)&g_M[(size_t)(kt + 32 + brow + 8 * p) * 3072 + col0 + bcv];
        }

#pragma unroll
        for (int ks = 0; ks < 4; ++ks) {
            int k = ks * 8;
            uint32_t af[4][4], bf[4][2];
#pragma unroll
            for (int mf = 0; mf < 4; ++mf) {
                int r = wm * 64 + mf * 16 + g;
                af[mf][0] = __float_as_uint(As[r][k + tg]);
                af[mf][1] = __float_as_uint(As[r + 8][k + tg]);
                af[mf][2] = __float_as_uint(As[r][k + tg + 4]);
                af[mf][3] = __float_as_uint(As[r + 8][k + tg + 4]);
            }
#pragma unroll
            for (int nf = 0; nf < 4; ++nf) {
                int cc = wn * 32 + nf * 8 + g;
                bf[nf][0] = __float_as_uint(Bs[k + tg][cc]);
                bf[nf][1] = __float_as_uint(Bs[k + tg + 4][cc]);
            }
#pragma unroll
            for (int mf = 0; mf < 4; ++mf)
#pragma unroll
                for (int nf = 0; nf < 4; ++nf)
                    mma_tf32(c[mf][nf], af[mf], bf[nf]);
        }
    }

    // epilogue: add bias, store
#pragma unroll
    for (int nf = 0; nf < 4; ++nf) {
        int cc = col0 + wn * 32 + nf * 8 + tg * 2;
        float b0 = bias[cc], b1 = bias[cc + 1];
#pragma unroll
        for (int mf = 0; mf < 4; ++mf) {
            int r = row0 + wm * 64 + mf * 16 + g;
            float2 v0 = make_float2(c[mf][nf][0] + b0, c[mf][nf][1] + b1);
            float2 v1 = make_float2(c[mf][nf][2] + b0, c[mf][nf][3] + b1);
            *(float2*)&Y[(size_t)r * 3072 + cc]       = v0;
            *(float2*)&Y[(size_t)(r + 8) * 3072 + cc] = v1;
        }
    }
}

// ---------------- launch -----------------------------------------------------
extern "C" void kernel_launch(void* const* d_in, const int* in_sizes, int n_in,
                              void* d_out, int out_size) {
    const float* x    = (const float*)d_in[0];
    const float* c0   = (const float*)d_in[1];
    const float* c1   = (const float*)d_in[2];
    const float* c2   = (const float*)d_in[3];
    const float* c3   = (const float*)d_in[4];
    const float* c4   = (const float*)d_in[5];
    const float* bias = (const float*)d_in[6];
    float* y = (float*)d_out;

    // 1) t1 = core0 x core1                      [192 x 192]
    k_t1<<<144, 256>>>(c0, c1);

    // 2) C = t1 x core2  (192 x 12288, K=192), then reindex -> t2
    {
        dim3 grid(12288 / 64, 192 / 64);
        gemm_mid<0><<<grid, 256>>>(c2, 192, 12288, 192);
    }
    k_reidx2<<<(48 * 128 * 384) / 256, 256>>>();

    // 3) C = t2 x core3  (6144 x 384, K=384), then reindex -> t3
    {
        dim3 grid(384 / 64, 6144 / 64);
        gemm_mid<1><<<grid, 256>>>(c3, 6144, 384, 384);
    }
    k_reidx3<<<(192 * 768 * 16) / 256, 256>>>();

    // 4) M = t3 x core4 (fused reindex)          [768 x 3072]
    k_t4<<<147456 / 256, 256>>>(c4);

    // 5) Y = X x M + bias   (32768 x 3072, K=768), tf32 tensor cores
    {
        dim3 grid(3072 / 128, 32768 / 128);
        k_main<<<grid, 256>>>(x, bias, y);
    }
}